// round 1
// baseline (speedup 1.0000x reference)
#include <cuda_runtime.h>

#define NEGINF (-1.0e30f)

// Persistent scratch (no allocations allowed)
__device__ float g_h[1568 * 128];
__device__ float g_q[1568 * 128];
__device__ float g_k[1568 * 128];
__device__ float g_v[1568 * 128];
__device__ float g_h1[1568 * 256];

// ---------------------------------------------------------------------------
// Embed: patchify (8,224,224)->(1568,256), tropical GEMM with embed_W[128,256],
// add pos. Output rows r = b*196+n, 128 cols.  BM=16, BN=128, 128 threads.
// ---------------------------------------------------------------------------
__global__ void embed_kernel(const float* __restrict__ x,
                             const float* __restrict__ eW,
                             const float* __restrict__ pos) {
    __shared__ float Xs[32 * 20];    // [kk][m], stride 20
    __shared__ float Ws[32 * 132];   // [kk][i], stride 132
    const int tid = threadIdx.x;
    const int r0 = blockIdx.x * 16;
    const int ty = tid >> 5;         // 0..3 -> rows ty*4
    const int tx = tid & 31;         // 0..31 -> cols tx*4

    float acc[4][4];
#pragma unroll
    for (int m = 0; m < 4; m++)
#pragma unroll
        for (int n = 0; n < 4; n++) acc[m][n] = NEGINF;

    for (int k0 = 0; k0 < 256; k0 += 32) {
#pragma unroll
        for (int t = 0; t < 4; t++) {
            int lin = tid + t * 128;
            int kk = lin & 31, m = lin >> 5;
            int r = r0 + m;
            int b = r / 196, n = r % 196;
            int gy = n / 14, gx = n % 14;
            int j = k0 + kk;
            int py = j >> 4, px = j & 15;
            Xs[kk * 20 + m] = x[(b * 224 + gy * 16 + py) * 224 + gx * 16 + px];
        }
#pragma unroll
        for (int t = 0; t < 32; t++) {
            int lin = tid + t * 128;
            int kk = lin & 31, i = lin >> 5;
            Ws[kk * 132 + i] = eW[i * 256 + k0 + kk];
        }
        __syncthreads();
#pragma unroll
        for (int kk = 0; kk < 32; kk++) {
            float4 xf = *(const float4*)(Xs + kk * 20 + ty * 4);
            float4 wf = *(const float4*)(Ws + kk * 132 + tx * 4);
            float xv[4] = {xf.x, xf.y, xf.z, xf.w};
            float wv[4] = {wf.x, wf.y, wf.z, wf.w};
#pragma unroll
            for (int m = 0; m < 4; m++)
#pragma unroll
                for (int n = 0; n < 4; n++)
                    acc[m][n] = fmaxf(acc[m][n], xv[m] + wv[n]);
        }
        __syncthreads();
    }

#pragma unroll
    for (int m = 0; m < 4; m++) {
        int r = r0 + ty * 4 + m;
        int nn = r % 196;
#pragma unroll
        for (int n = 0; n < 4; n++) {
            int col = tx * 4 + n;
            g_h[r * 128 + col] = acc[m][n] + pos[nn * 128 + col];
        }
    }
}

// ---------------------------------------------------------------------------
// QKV: xn = pnorm(h) then tropical GEMM with one of {qW,kW,vW} (blockIdx.y).
// BM=32, BN=128, K=128, 256 threads.  grid (49, 3).
// ---------------------------------------------------------------------------
__global__ void qkv_kernel(const float* __restrict__ qW,
                           const float* __restrict__ kW,
                           const float* __restrict__ vW) {
    __shared__ float Xs[128 * 36];   // [k][m], stride 36
    __shared__ float Ws[32 * 132];
    __shared__ float red[32 * 8];
    __shared__ float rmax[32];
    const int tid = threadIdx.x;
    const int r0 = blockIdx.x * 32;

#pragma unroll
    for (int t = 0; t < 16; t++) {
        int lin = tid + t * 256;
        int kk = lin & 127, m = lin >> 7;
        Xs[kk * 36 + m] = g_h[(r0 + m) * 128 + kk];
    }
    __syncthreads();
    {
        int sub = tid & 7, m = tid >> 3;
        float mx = NEGINF;
        for (int k = sub; k < 128; k += 8) mx = fmaxf(mx, Xs[k * 36 + m]);
        red[m * 8 + sub] = mx;
    }
    __syncthreads();
    if (tid < 32) {
        float mx = red[tid * 8];
#pragma unroll
        for (int s = 1; s < 8; s++) mx = fmaxf(mx, red[tid * 8 + s]);
        rmax[tid] = mx;
    }
    __syncthreads();
#pragma unroll
    for (int t = 0; t < 16; t++) {
        int lin = tid + t * 256;
        int kk = lin & 127, m = lin >> 7;
        Xs[kk * 36 + m] -= rmax[m];
    }

    const float* W = (blockIdx.y == 0) ? qW : ((blockIdx.y == 1) ? kW : vW);
    float* O = (blockIdx.y == 0) ? g_q : ((blockIdx.y == 1) ? g_k : g_v);
    const int ty = tid >> 5;   // 0..7 -> rows ty*4
    const int tx = tid & 31;   // cols tx*4

    float acc[4][4];
#pragma unroll
    for (int m = 0; m < 4; m++)
#pragma unroll
        for (int n = 0; n < 4; n++) acc[m][n] = NEGINF;

    for (int k0 = 0; k0 < 128; k0 += 32) {
        __syncthreads();
#pragma unroll
        for (int t = 0; t < 16; t++) {
            int lin = tid + t * 256;
            int kk = lin & 31, i = lin >> 5;
            Ws[kk * 132 + i] = W[i * 128 + k0 + kk];
        }
        __syncthreads();
#pragma unroll
        for (int kk = 0; kk < 32; kk++) {
            float4 xf = *(const float4*)(Xs + (k0 + kk) * 36 + ty * 4);
            float4 wf = *(const float4*)(Ws + kk * 132 + tx * 4);
            float xv[4] = {xf.x, xf.y, xf.z, xf.w};
            float wv[4] = {wf.x, wf.y, wf.z, wf.w};
#pragma unroll
            for (int m = 0; m < 4; m++)
#pragma unroll
                for (int n = 0; n < 4; n++)
                    acc[m][n] = fmaxf(acc[m][n], xv[m] + wv[n]);
        }
    }
#pragma unroll
    for (int m = 0; m < 4; m++) {
        int r = r0 + ty * 4 + m;
#pragma unroll
        for (int n = 0; n < 4; n++)
            O[r * 128 + tx * 4 + n] = acc[m][n];
    }
}

// ---------------------------------------------------------------------------
// Attention, flash style.  Per CTA: batch b, 16 q-rows.  128 threads.
// O[i,d] = max_j( max_d'(q+k) + v );  a = O - rowmax_d(O);  h = max(h, a).
// (scores rowmax subtraction provably cancels.)  grid (13, 8).
// ---------------------------------------------------------------------------
__global__ void attn_kernel() {
    __shared__ float Qs[128 * 20];   // [d][i]
    __shared__ float Ks[128 * 34];   // [d][j]
    __shared__ float Vs[32 * 132];   // [j][d]
    __shared__ float Ss[32 * 18];    // [j][i]
    __shared__ float red[16 * 16];
    const int tid = threadIdx.x;
    const int b = blockIdx.y;
    const int i0 = blockIdx.x * 16;
    const int ty = tid >> 4;   // 0..7
    const int tx = tid & 15;   // 0..15

#pragma unroll
    for (int t = 0; t < 16; t++) {
        int lin = tid + t * 128;
        int d = lin & 127, i = lin >> 7;
        Qs[d * 20 + i] = (i0 + i < 196) ? g_q[(b * 196 + i0 + i) * 128 + d] : NEGINF;
    }

    float o0[8], o1[8];
#pragma unroll
    for (int n = 0; n < 8; n++) { o0[n] = NEGINF; o1[n] = NEGINF; }

    for (int j0 = 0; j0 < 196; j0 += 32) {
        __syncthreads();
#pragma unroll
        for (int t = 0; t < 32; t++) {
            int lin = tid + t * 128;
            int d = lin & 127, j = lin >> 7;
            bool ok = (j0 + j) < 196;
            int r = b * 196 + j0 + j;
            Ks[d * 34 + j] = ok ? g_k[r * 128 + d] : NEGINF;
            Vs[j * 132 + d] = ok ? g_v[r * 128 + d] : NEGINF;
        }
        __syncthreads();

        // S = max_d (Q + K), 16x32 tile, 2x2 per thread
        float s00 = NEGINF, s01 = NEGINF, s10 = NEGINF, s11 = NEGINF;
#pragma unroll 8
        for (int d = 0; d < 128; d++) {
            float2 qf = *(const float2*)(Qs + d * 20 + ty * 2);
            float2 kf = *(const float2*)(Ks + d * 34 + tx * 2);
            s00 = fmaxf(s00, qf.x + kf.x);
            s01 = fmaxf(s01, qf.x + kf.y);
            s10 = fmaxf(s10, qf.y + kf.x);
            s11 = fmaxf(s11, qf.y + kf.y);
        }
        Ss[(tx * 2 + 0) * 18 + ty * 2 + 0] = s00;
        Ss[(tx * 2 + 1) * 18 + ty * 2 + 0] = s01;
        Ss[(tx * 2 + 0) * 18 + ty * 2 + 1] = s10;
        Ss[(tx * 2 + 1) * 18 + ty * 2 + 1] = s11;
        __syncthreads();

        // O update: 16x128 tile, 2x8 per thread
#pragma unroll 8
        for (int j = 0; j < 32; j++) {
            float2 sf = *(const float2*)(Ss + j * 18 + ty * 2);
            float4 va = *(const float4*)(Vs + j * 132 + tx * 8);
            float4 vb = *(const float4*)(Vs + j * 132 + tx * 8 + 4);
            float vv[8] = {va.x, va.y, va.z, va.w, vb.x, vb.y, vb.z, vb.w};
#pragma unroll
            for (int n = 0; n < 8; n++) {
                o0[n] = fmaxf(o0[n], sf.x + vv[n]);
                o1[n] = fmaxf(o1[n], sf.y + vv[n]);
            }
        }
    }
    __syncthreads();

    // rowmax over d (across 16 tx threads per row)
    float p0 = NEGINF, p1 = NEGINF;
#pragma unroll
    for (int n = 0; n < 8; n++) { p0 = fmaxf(p0, o0[n]); p1 = fmaxf(p1, o1[n]); }
    red[(ty * 2 + 0) * 16 + tx] = p0;
    red[(ty * 2 + 1) * 16 + tx] = p1;
    __syncthreads();
    float rm0 = NEGINF, rm1 = NEGINF;
#pragma unroll
    for (int s = 0; s < 16; s++) {
        rm0 = fmaxf(rm0, red[(ty * 2 + 0) * 16 + s]);
        rm1 = fmaxf(rm1, red[(ty * 2 + 1) * 16 + s]);
    }

    int i_a = ty * 2 + 0, i_b = ty * 2 + 1;
    if (i0 + i_a < 196) {
        int base = (b * 196 + i0 + i_a) * 128 + tx * 8;
#pragma unroll
        for (int n = 0; n < 8; n++)
            g_h[base + n] = fmaxf(g_h[base + n], o0[n] - rm0);
    }
    if (i0 + i_b < 196) {
        int base = (b * 196 + i0 + i_b) * 128 + tx * 8;
#pragma unroll
        for (int n = 0; n < 8; n++)
            g_h[base + n] = fmaxf(g_h[base + n], o1[n] - rm1);
    }
}

// ---------------------------------------------------------------------------
// FF1: xn = pnorm(h); h1 = max(tropmm(xn, f1W), tau).  M=1568,K=128,Nout=256.
// grid (49, 2): blockIdx.y selects the 128-wide output half. 256 threads.
// ---------------------------------------------------------------------------
__global__ void ff1_kernel(const float* __restrict__ W1,
                           const float* __restrict__ tau) {
    __shared__ float Xs[128 * 36];
    __shared__ float Ws[32 * 132];
    __shared__ float red[32 * 8];
    __shared__ float rmax[32];
    const int tid = threadIdx.x;
    const int r0 = blockIdx.x * 32;
    const int h0 = blockIdx.y * 128;

#pragma unroll
    for (int t = 0; t < 16; t++) {
        int lin = tid + t * 256;
        int kk = lin & 127, m = lin >> 7;
        Xs[kk * 36 + m] = g_h[(r0 + m) * 128 + kk];
    }
    __syncthreads();
    {
        int sub = tid & 7, m = tid >> 3;
        float mx = NEGINF;
        for (int k = sub; k < 128; k += 8) mx = fmaxf(mx, Xs[k * 36 + m]);
        red[m * 8 + sub] = mx;
    }
    __syncthreads();
    if (tid < 32) {
        float mx = red[tid * 8];
#pragma unroll
        for (int s = 1; s < 8; s++) mx = fmaxf(mx, red[tid * 8 + s]);
        rmax[tid] = mx;
    }
    __syncthreads();
#pragma unroll
    for (int t = 0; t < 16; t++) {
        int lin = tid + t * 256;
        int kk = lin & 127, m = lin >> 7;
        Xs[kk * 36 + m] -= rmax[m];
    }

    const int ty = tid >> 5, tx = tid & 31;
    float acc[4][4];
#pragma unroll
    for (int m = 0; m < 4; m++)
#pragma unroll
        for (int n = 0; n < 4; n++) acc[m][n] = NEGINF;

    for (int k0 = 0; k0 < 128; k0 += 32) {
        __syncthreads();
#pragma unroll
        for (int t = 0; t < 16; t++) {
            int lin = tid + t * 256;
            int kk = lin & 31, i = lin >> 5;
            Ws[kk * 132 + i] = W1[(h0 + i) * 128 + k0 + kk];
        }
        __syncthreads();
#pragma unroll
        for (int kk = 0; kk < 32; kk++) {
            float4 xf = *(const float4*)(Xs + (k0 + kk) * 36 + ty * 4);
            float4 wf = *(const float4*)(Ws + kk * 132 + tx * 4);
            float xv[4] = {xf.x, xf.y, xf.z, xf.w};
            float wv[4] = {wf.x, wf.y, wf.z, wf.w};
#pragma unroll
            for (int m = 0; m < 4; m++)
#pragma unroll
                for (int n = 0; n < 4; n++)
                    acc[m][n] = fmaxf(acc[m][n], xv[m] + wv[n]);
        }
    }
    float tv = tau[0];
#pragma unroll
    for (int m = 0; m < 4; m++) {
        int r = r0 + ty * 4 + m;
#pragma unroll
        for (int n = 0; n < 4; n++)
            g_h1[r * 256 + h0 + tx * 4 + n] = fmaxf(acc[m][n], tv);
    }
}

// ---------------------------------------------------------------------------
// FF2: ff = pnorm(tropmm(h1, f2W)); h = max(h, ff).  M=1568,K=256,Nout=128.
// BM=16, 128 threads, grid 98.
// ---------------------------------------------------------------------------
__global__ void ff2_kernel(const float* __restrict__ W2) {
    __shared__ float Xs[256 * 20];
    __shared__ float Ws[16 * 132];
    __shared__ float red[16 * 32];
    const int tid = threadIdx.x;
    const int r0 = blockIdx.x * 16;

#pragma unroll
    for (int t = 0; t < 32; t++) {
        int lin = tid + t * 128;
        int kk = lin & 255, m = lin >> 8;
        Xs[kk * 20 + m] = g_h1[(r0 + m) * 256 + kk];
    }

    const int ty = tid >> 5, tx = tid & 31;   // rows ty*4 (16), cols tx*4 (128)
    float acc[4][4];
#pragma unroll
    for (int m = 0; m < 4; m++)
#pragma unroll
        for (int n = 0; n < 4; n++) acc[m][n] = NEGINF;

    for (int k0 = 0; k0 < 256; k0 += 16) {
        __syncthreads();
#pragma unroll
        for (int t = 0; t < 16; t++) {
            int lin = tid + t * 128;
            int kk = lin & 15, i = lin >> 4;
            Ws[kk * 132 + i] = W2[i * 256 + k0 + kk];
        }
        __syncthreads();
#pragma unroll
        for (int kk = 0; kk < 16; kk++) {
            float4 xf = *(const float4*)(Xs + (k0 + kk) * 20 + ty * 4);
            float4 wf = *(const float4*)(Ws + kk * 132 + tx * 4);
            float xv[4] = {xf.x, xf.y, xf.z, xf.w};
            float wv[4] = {wf.x, wf.y, wf.z, wf.w};
#pragma unroll
            for (int m = 0; m < 4; m++)
#pragma unroll
                for (int n = 0; n < 4; n++)
                    acc[m][n] = fmaxf(acc[m][n], xv[m] + wv[n]);
        }
    }
    __syncthreads();
#pragma unroll
    for (int m = 0; m < 4; m++) {
        float pm = fmaxf(fmaxf(acc[m][0], acc[m][1]), fmaxf(acc[m][2], acc[m][3]));
        red[(ty * 4 + m) * 32 + tx] = pm;
    }
    __syncthreads();
#pragma unroll
    for (int m = 0; m < 4; m++) {
        int row = ty * 4 + m;
        float rm = NEGINF;
#pragma unroll
        for (int s = 0; s < 32; s++) rm = fmaxf(rm, red[row * 32 + s]);
        int base = (r0 + row) * 128 + tx * 4;
#pragma unroll
        for (int n = 0; n < 4; n++)
            g_h[base + n] = fmaxf(g_h[base + n], acc[m][n] - rm);
    }
}

// ---------------------------------------------------------------------------
// Pool over patches + head tropical GEMM + logit scale. grid (8 batches, 8
// class tiles of 125), 128 threads.
// ---------------------------------------------------------------------------
__global__ void head_kernel(const float* __restrict__ hW,
                            const float* __restrict__ ls,
                            float* __restrict__ out) {
    __shared__ float pooled[128];
    const int b = blockIdx.x, ct = blockIdx.y, tid = threadIdx.x;

    const float* hp = g_h + (b * 196) * 128 + tid;
    float m0 = NEGINF, m1 = NEGINF, m2 = NEGINF, m3 = NEGINF;
#pragma unroll 4
    for (int n = 0; n < 196; n += 4) {
        m0 = fmaxf(m0, hp[(n + 0) * 128]);
        m1 = fmaxf(m1, hp[(n + 1) * 128]);
        m2 = fmaxf(m2, hp[(n + 2) * 128]);
        m3 = fmaxf(m3, hp[(n + 3) * 128]);
    }
    pooled[tid] = fmaxf(fmaxf(m0, m1), fmaxf(m2, m3));
    __syncthreads();

    int c = ct * 125 + tid;
    if (tid < 125) {
        const float* w = hW + c * 128;
        float a = NEGINF;
#pragma unroll 8
        for (int d = 0; d < 128; d++) a = fmaxf(a, pooled[d] + w[d]);
        out[b * 1000 + c] = a * ls[0];
    }
}

// ---------------------------------------------------------------------------
extern "C" void kernel_launch(void* const* d_in, const int* in_sizes, int n_in,
                              void* d_out, int out_size) {
    const float* x   = (const float*)d_in[0];
    const float* eW  = (const float*)d_in[1];
    const float* pos = (const float*)d_in[2];
    const float* qW[2]  = {(const float*)d_in[3],  (const float*)d_in[9]};
    const float* kW[2]  = {(const float*)d_in[4],  (const float*)d_in[10]};
    const float* vW[2]  = {(const float*)d_in[5],  (const float*)d_in[11]};
    const float* f1W[2] = {(const float*)d_in[6],  (const float*)d_in[12]};
    const float* f2W[2] = {(const float*)d_in[7],  (const float*)d_in[13]};
    const float* tau[2] = {(const float*)d_in[8],  (const float*)d_in[14]};
    const float* hW  = (const float*)d_in[15];
    const float* ls  = (const float*)d_in[16];
    float* out = (float*)d_out;

    embed_kernel<<<98, 128>>>(x, eW, pos);
    for (int l = 0; l < 2; l++) {
        qkv_kernel<<<dim3(49, 3), 256>>>(qW[l], kW[l], vW[l]);
        attn_kernel<<<dim3(13, 8), 128>>>();
        ff1_kernel<<<dim3(49, 2), 256>>>(f1W[l], tau[l]);
        ff2_kernel<<<98, 128>>>(f2W[l]);
    }
    head_kernel<<<dim3(8, 8), 128>>>(hW, ls, out);
}